// round 14
// baseline (speedup 1.0000x reference)
#include <cuda_runtime.h>

#define B_   16
#define T_   512
#define C_   8
#define S_   64
#define KSZ_ 32
#define TOUT 481
#define EPSF 1e-8f

// Scratch (allocation-free rule: __device__ globals). g_xt padded +64 so the
// 3x float4 window loads at the t-edge stay in-bounds (values masked at store).
__device__ float g_xt[B_ * C_ * T_ + 64];   // x norm, transposed [b][ch][t]
// Kernel slab in FINAL per-k layout: [k][s][8 x float4] = 128B per (k,s) entry:
//   float2 e=0..7 : broadcast pairs (-kn,-kn) for c=0..7
//   float2 e=8    : (q2/2, q2/2)
//   e=9..15       : padding (never read)
__device__ float4 g_slab[KSZ_ * S_ * 8];

// ---- packed f32x2 helpers (sm_100a) ---------------------------------------
__device__ __forceinline__ unsigned long long pk2(float lo, float hi) {
    unsigned long long r;
    asm("mov.b64 %0, {%1, %2};" : "=l"(r) : "f"(lo), "f"(hi));
    return r;
}
__device__ __forceinline__ unsigned long long fma2(unsigned long long a,
                                                   unsigned long long b,
                                                   unsigned long long c) {
    unsigned long long d;
    asm("fma.rn.f32x2 %0, %1, %2, %3;" : "=l"(d) : "l"(a), "l"(b), "l"(c));
    return d;
}
__device__ __forceinline__ unsigned long long mul2(unsigned long long a,
                                                   unsigned long long b) {
    unsigned long long d;
    asm("mul.rn.f32x2 %0, %1, %2;" : "=l"(d) : "l"(a), "l"(b));
    return d;
}
__device__ __forceinline__ void unpk2(unsigned long long v, float& lo, float& hi) {
    asm("mov.b64 {%0, %1}, %2;" : "=f"(lo), "=f"(hi) : "l"(v));
}

// ---- warp reduction (sum) -------------------------------------------------
__device__ __forceinline__ float wred(float v) {
    v += __shfl_xor_sync(0xFFFFFFFF, v, 16);
    v += __shfl_xor_sync(0xFFFFFFFF, v, 8);
    v += __shfl_xor_sync(0xFFFFFFFF, v, 4);
    v += __shfl_xor_sync(0xFFFFFFFF, v, 2);
    v += __shfl_xor_sync(0xFFFFFFFF, v, 1);
    return v;
}

// ---------------------------------------------------------------------------
// Prep: blocks [0,128) normalize x per (b,ch) over T and transpose;
//       blocks [128,192) normalize kernel per s, writing the padded slab
//       layout (negated broadcast pairs + hq2). Shuffle-based reductions.
// ---------------------------------------------------------------------------
__global__ __launch_bounds__(256) void lsd_prep(const float* __restrict__ x,
                                                const float* __restrict__ kern) {
    const int bid = blockIdx.x;
    const int tid = threadIdx.x;
    const int lid = tid & 31;
    const int wid = tid >> 5;
    __shared__ float pr0[8];
    __shared__ float pr1[8];
    __shared__ float stats[2];          // mean, inv
    __shared__ float kns[256];

    if (bid < B_ * C_) {
        const int b = bid >> 3, ch = bid & 7;
        const float v0 = x[(b * T_ + tid) * C_ + ch];
        const float v1 = x[(b * T_ + tid + 256) * C_ + ch];
        const float s0 = wred(v0 + v1);
        const float s1 = wred(v0 * v0 + v1 * v1);
        if (lid == 0) { pr0[wid] = s0; pr1[wid] = s1; }
        __syncthreads();
        if (wid == 0) {
            float a0 = (lid < 8) ? pr0[lid] : 0.0f;
            float a1 = (lid < 8) ? pr1[lid] : 0.0f;
            a0 = wred(a0); a1 = wred(a1);
            if (lid == 0) {
                const float mean = a0 * (1.0f / T_);
                const float var  = a1 * (1.0f / T_) - mean * mean;
                stats[0] = mean;
                stats[1] = 1.0f / (sqrtf(fmaxf(var, 0.0f)) + EPSF);
            }
        }
        __syncthreads();
        const float mean = stats[0], inv = stats[1];
        float* xr = &g_xt[(b * C_ + ch) * T_];
        xr[tid]       = (v0 - mean) * inv;
        xr[tid + 256] = (v1 - mean) * inv;
    } else {
        const int s = bid - B_ * C_;
        const float v = kern[s * 256 + tid];
        const float s0 = wred(v);
        const float s1 = wred(v * v);
        if (lid == 0) { pr0[wid] = s0; pr1[wid] = s1; }
        __syncthreads();
        if (wid == 0) {
            float a0 = (lid < 8) ? pr0[lid] : 0.0f;
            float a1 = (lid < 8) ? pr1[lid] : 0.0f;
            a0 = wred(a0); a1 = wred(a1);
            if (lid == 0) {
                const float mean = a0 * (1.0f / 256.0f);
                const float var  = a1 * (1.0f / 256.0f) - mean * mean;
                stats[0] = mean;
                stats[1] = 1.0f / (sqrtf(fmaxf(var, 0.0f)) + EPSF);
            }
        }
        __syncthreads();
        const float kn = (v - stats[0]) * stats[1];
        kns[tid] = kn;
        // slab entry [k][s], float2 element c: (-kn, -kn)
        const int k = tid >> 3, c = tid & 7;
        ((float2*)g_slab)[(k * S_ + s) * 16 + c] = make_float2(-kn, -kn);
        __syncthreads();
        if (tid < KSZ_) {
            float q2 = 0.0f;
            #pragma unroll
            for (int c2 = 0; c2 < 8; c2++) {
                const float t = kns[tid * 8 + c2];
                q2 = fmaf(t, t, q2);
            }
            const float h = 0.5f * q2;
            ((float2*)g_slab)[(tid * S_ + s) * 16 + 8] = make_float2(h, h);
        }
    }
}

// ---------------------------------------------------------------------------
// Main, j=4, 128-THREAD BLOCKS (one k per block; k/ch/m block-uniform):
//   grid = (128, 16): blockIdx.y = b, blockIdx.x = tb*32 + k (tb in 0..3)
//   block = 128 thr = 4 warps: warp w = sg (S-quarter, 16 s each)
//   lane l handles t = tb*128 + l*4 + j, j in [0,4).
// 2048 blocks of 4 warps -> 8192 warp-units; 10 blocks/SM at 51 regs
// (launch_bounds(128,10)), waves = 1.38 with fine-grained tail.
// Slab (1 k x 64 s x 128B = 8KB) staged in smem; broadcast LDS in hot loop.
// acc_{j,j+1} = (q2/2 - dot_j, q2/2 - dot_{j+1}); out = p2 + 2*min.
// ---------------------------------------------------------------------------
__global__ __launch_bounds__(128, 10) void lsd_main(float* __restrict__ out) {
    const int tid = threadIdx.x;
    const int l   = tid & 31;
    const int sg  = tid >> 5;                 // 0..3 (warp-uniform)
    const int b   = blockIdx.y;
    const int tb  = blockIdx.x >> 5;          // 0..3
    const int k   = blockIdx.x & 31;          // BLOCK-uniform
    const int ch  = k >> 2;
    const int m   = k & 3;

    __shared__ float4 smq4[64 * 8];           // 8KB: [s][8 float4]
    __shared__ float s_mn[3 * 128];           // 1.5KB: [sg-1][l*4 + j]

    // ---- slab copy: 512 float4 over 128 threads ----
    {
        const float4* __restrict__ gsl = g_slab + k * 512;
        #pragma unroll
        for (int it = 0; it < 4; it++) {
            const int idx = tid + it * 128;
            smq4[idx] = gsl[idx];
        }
    }

    // ---- window loads: 12 floats via 3 aligned float4 LDGs (11 used) ----
    const int t0     = tb * 128 + l * 4;
    const int wstart = t0 + 8 * m;            // multiple of 4 -> 16B aligned
    const float4* __restrict__ xv =
        (const float4*)(g_xt + (b * C_ + ch) * T_ + wstart);
    const float4 A = xv[0], Bv = xv[1], Cv = xv[2];
    float wv[11];
    wv[0] = A.x;  wv[1] = A.y;  wv[2] = A.z;  wv[3] = A.w;
    wv[4] = Bv.x; wv[5] = Bv.y; wv[6] = Bv.z; wv[7] = Bv.w;
    wv[8] = Cv.x; wv[9] = Cv.y; wv[10] = Cv.z;

    unsigned long long a[10];
    #pragma unroll
    for (int i = 0; i < 10; i++) a[i] = pk2(wv[i], wv[i + 1]);

    __syncthreads();

    // warp-uniform smem base for this warp's S-quarter (16B units)
    const ulonglong2* __restrict__ qv =
        (const ulonglong2*)smq4 + sg * 16 * 8;

    float mn[4];
    #pragma unroll
    for (int j = 0; j < 4; j++) mn[j] = 3.4e38f;

    #pragma unroll
    for (int s = 0; s < 16; s++) {
        const ulonglong2 u0 = qv[s * 8 + 0];      // qq0, qq1 (negated)
        const ulonglong2 u1 = qv[s * 8 + 1];      // qq2, qq3
        const ulonglong2 u2 = qv[s * 8 + 2];      // qq4, qq5
        const ulonglong2 u3 = qv[s * 8 + 3];      // qq6, qq7
        const unsigned long long hq2 =
            *(const unsigned long long*)(qv + s * 8 + 4);

        unsigned long long accA = fma2(a[0], u0.x, hq2);
        unsigned long long accB = fma2(a[2], u0.x, hq2);
        accA = fma2(a[1], u0.y, accA);
        accB = fma2(a[3], u0.y, accB);
        accA = fma2(a[2], u1.x, accA);
        accB = fma2(a[4], u1.x, accB);
        accA = fma2(a[3], u1.y, accA);
        accB = fma2(a[5], u1.y, accB);
        accA = fma2(a[4], u2.x, accA);
        accB = fma2(a[6], u2.x, accB);
        accA = fma2(a[5], u2.y, accA);
        accB = fma2(a[7], u2.y, accB);
        accA = fma2(a[6], u3.x, accA);
        accB = fma2(a[8], u3.x, accB);
        accA = fma2(a[7], u3.y, accA);
        accB = fma2(a[9], u3.y, accB);

        float d0, d1;
        unpk2(accA, d0, d1);
        mn[0] = fminf(mn[0], d0);
        mn[1] = fminf(mn[1], d1);
        unpk2(accB, d0, d1);
        mn[2] = fminf(mn[2], d0);
        mn[3] = fminf(mn[3], d1);
    }

    // merge the four S-quarters (index within block: l*4 + j)
    if (sg >= 1) {
        #pragma unroll
        for (int j = 0; j < 4; j++)
            s_mn[(sg - 1) * 128 + l * 4 + j] = mn[j];
    }
    __syncthreads();
    if (sg == 0) {
        // packed p2: (p2_0,p2_1) from a[0..7], (p2_2,p2_3) from a[2..9]
        unsigned long long pA = mul2(a[0], a[0]);
        unsigned long long pB = mul2(a[2], a[2]);
        #pragma unroll
        for (int c = 1; c < 8; c++) {
            pA = fma2(a[c], a[c], pA);
            pB = fma2(a[c + 2], a[c + 2], pB);
        }
        float p2j[4];
        unpk2(pA, p2j[0], p2j[1]);
        unpk2(pB, p2j[2], p2j[3]);

        #pragma unroll
        for (int j = 0; j < 4; j++) {
            const int t = t0 + j;
            if (t < TOUT) {
                const int base = l * 4 + j;
                float v = mn[j];
                v = fminf(v, s_mn[0 * 128 + base]);
                v = fminf(v, s_mn[1 * 128 + base]);
                v = fminf(v, s_mn[2 * 128 + base]);
                out[(b * TOUT + t) * KSZ_ + k] = fmaf(2.0f, v, p2j[j]);
            }
        }
    }
}

extern "C" void kernel_launch(void* const* d_in, const int* in_sizes, int n_in,
                              void* d_out, int out_size) {
    const float* x    = (const float*)d_in[0];   // (16, 512, 8) f32
    const float* kern = (const float*)d_in[1];   // (64, 32, 8) f32
    float* out = (float*)d_out;                  // (16, 481, 32) f32

    lsd_prep<<<B_ * C_ + S_, 256>>>(x, kern);
    dim3 grid(128, B_);                          // (tb*32 + k) x b
    lsd_main<<<grid, 128>>>(out);
}

// round 15
// speedup vs baseline: 1.0544x; 1.0544x over previous
#include <cuda_runtime.h>

#define B_   16
#define T_   512
#define C_   8
#define S_   64
#define KSZ_ 32
#define TOUT 481
#define EPSF 1e-8f

// Scratch (allocation-free rule: __device__ globals). g_xt padded +64 so the
// 4x float4 window loads at the t-edge stay in-bounds (values masked at store).
__device__ float g_xt[B_ * C_ * T_ + 64];   // x norm, transposed [b][ch][t]
// Kernel slab, 2s-PACKED per-k layout: for each (k, sp = s>>1): 9 x float4:
//   slot 0..3 : s = 2sp   broadcast pairs (-kn,-kn), c-pairs (0,1)..(6,7)
//   slot 4..7 : s = 2sp+1 broadcast pairs
//   slot 8    : (h0, h0, h1, h1)  where h = q2/2 for s=2sp, 2sp+1
// One k = 32 sp x 9 x 16B = 4608B.  Hot loop: 9 LDS.128 per 2 s.
__device__ float4 g_slab[KSZ_ * 32 * 9];

// ---- packed f32x2 helpers (sm_100a) ---------------------------------------
__device__ __forceinline__ unsigned long long pk2(float lo, float hi) {
    unsigned long long r;
    asm("mov.b64 %0, {%1, %2};" : "=l"(r) : "f"(lo), "f"(hi));
    return r;
}
__device__ __forceinline__ unsigned long long fma2(unsigned long long a,
                                                   unsigned long long b,
                                                   unsigned long long c) {
    unsigned long long d;
    asm("fma.rn.f32x2 %0, %1, %2, %3;" : "=l"(d) : "l"(a), "l"(b), "l"(c));
    return d;
}
__device__ __forceinline__ void unpk2(unsigned long long v, float& lo, float& hi) {
    asm("mov.b64 {%0, %1}, %2;" : "=f"(lo), "=f"(hi) : "l"(v));
}

// ---- warp reduction (sum) -------------------------------------------------
__device__ __forceinline__ float wred(float v) {
    v += __shfl_xor_sync(0xFFFFFFFF, v, 16);
    v += __shfl_xor_sync(0xFFFFFFFF, v, 8);
    v += __shfl_xor_sync(0xFFFFFFFF, v, 4);
    v += __shfl_xor_sync(0xFFFFFFFF, v, 2);
    v += __shfl_xor_sync(0xFFFFFFFF, v, 1);
    return v;
}

// ---- one s-step: acc = hq2 + sum_c a[j+c]*(-q_c), min into mn[0..7] -------
__device__ __forceinline__ void step8(const ulonglong2& u0, const ulonglong2& u1,
                                      const ulonglong2& u2, const ulonglong2& u3,
                                      unsigned long long hq2,
                                      const unsigned long long* a, float* mn) {
    unsigned long long accA = fma2(a[0], u0.x, hq2);
    unsigned long long accB = fma2(a[2], u0.x, hq2);
    unsigned long long accC = fma2(a[4], u0.x, hq2);
    unsigned long long accD = fma2(a[6], u0.x, hq2);
    accA = fma2(a[1], u0.y, accA);
    accB = fma2(a[3], u0.y, accB);
    accC = fma2(a[5], u0.y, accC);
    accD = fma2(a[7], u0.y, accD);
    accA = fma2(a[2], u1.x, accA);
    accB = fma2(a[4], u1.x, accB);
    accC = fma2(a[6], u1.x, accC);
    accD = fma2(a[8], u1.x, accD);
    accA = fma2(a[3], u1.y, accA);
    accB = fma2(a[5], u1.y, accB);
    accC = fma2(a[7], u1.y, accC);
    accD = fma2(a[9], u1.y, accD);
    accA = fma2(a[4], u2.x, accA);
    accB = fma2(a[6], u2.x, accB);
    accC = fma2(a[8], u2.x, accC);
    accD = fma2(a[10], u2.x, accD);
    accA = fma2(a[5], u2.y, accA);
    accB = fma2(a[7], u2.y, accB);
    accC = fma2(a[9], u2.y, accC);
    accD = fma2(a[11], u2.y, accD);
    accA = fma2(a[6], u3.x, accA);
    accB = fma2(a[8], u3.x, accB);
    accC = fma2(a[10], u3.x, accC);
    accD = fma2(a[12], u3.x, accD);
    accA = fma2(a[7], u3.y, accA);
    accB = fma2(a[9], u3.y, accB);
    accC = fma2(a[11], u3.y, accC);
    accD = fma2(a[13], u3.y, accD);

    float d0, d1;
    unpk2(accA, d0, d1);
    mn[0] = fminf(mn[0], d0);
    mn[1] = fminf(mn[1], d1);
    unpk2(accB, d0, d1);
    mn[2] = fminf(mn[2], d0);
    mn[3] = fminf(mn[3], d1);
    unpk2(accC, d0, d1);
    mn[4] = fminf(mn[4], d0);
    mn[5] = fminf(mn[5], d1);
    unpk2(accD, d0, d1);
    mn[6] = fminf(mn[6], d0);
    mn[7] = fminf(mn[7], d1);
}

// ---------------------------------------------------------------------------
// Prep: blocks [0,128) normalize x per (b,ch) over T and transpose;
//       blocks [128,192) normalize kernel per s, writing the 2s-packed slab
//       layout (negated broadcast pairs + packed hq2). Shuffle reductions.
// ---------------------------------------------------------------------------
__global__ __launch_bounds__(256) void lsd_prep(const float* __restrict__ x,
                                                const float* __restrict__ kern) {
    const int bid = blockIdx.x;
    const int tid = threadIdx.x;
    const int lid = tid & 31;
    const int wid = tid >> 5;
    __shared__ float pr0[8];
    __shared__ float pr1[8];
    __shared__ float stats[2];          // mean, inv
    __shared__ float kns[256];

    if (bid < B_ * C_) {
        const int b = bid >> 3, ch = bid & 7;
        const float v0 = x[(b * T_ + tid) * C_ + ch];
        const float v1 = x[(b * T_ + tid + 256) * C_ + ch];
        const float s0 = wred(v0 + v1);
        const float s1 = wred(v0 * v0 + v1 * v1);
        if (lid == 0) { pr0[wid] = s0; pr1[wid] = s1; }
        __syncthreads();
        if (wid == 0) {
            float a0 = (lid < 8) ? pr0[lid] : 0.0f;
            float a1 = (lid < 8) ? pr1[lid] : 0.0f;
            a0 = wred(a0); a1 = wred(a1);
            if (lid == 0) {
                const float mean = a0 * (1.0f / T_);
                const float var  = a1 * (1.0f / T_) - mean * mean;
                stats[0] = mean;
                stats[1] = 1.0f / (sqrtf(fmaxf(var, 0.0f)) + EPSF);
            }
        }
        __syncthreads();
        const float mean = stats[0], inv = stats[1];
        float* xr = &g_xt[(b * C_ + ch) * T_];
        xr[tid]       = (v0 - mean) * inv;
        xr[tid + 256] = (v1 - mean) * inv;
    } else {
        const int s = bid - B_ * C_;
        const float v = kern[s * 256 + tid];
        const float s0 = wred(v);
        const float s1 = wred(v * v);
        if (lid == 0) { pr0[wid] = s0; pr1[wid] = s1; }
        __syncthreads();
        if (wid == 0) {
            float a0 = (lid < 8) ? pr0[lid] : 0.0f;
            float a1 = (lid < 8) ? pr1[lid] : 0.0f;
            a0 = wred(a0); a1 = wred(a1);
            if (lid == 0) {
                const float mean = a0 * (1.0f / 256.0f);
                const float var  = a1 * (1.0f / 256.0f) - mean * mean;
                stats[0] = mean;
                stats[1] = 1.0f / (sqrtf(fmaxf(var, 0.0f)) + EPSF);
            }
        }
        __syncthreads();
        const float kn = (v - stats[0]) * stats[1];
        kns[tid] = kn;
        // 2s-packed slab write: entry (k, sp=s>>1), half h=s&1:
        // float2 index = ((k*32+sp)*9 + h*4 + (c>>1))*2 + (c&1)
        const int k = tid >> 3, c = tid & 7;
        const int sp = s >> 1, h = s & 1;
        ((float2*)g_slab)[(((k * 32 + sp) * 9) + h * 4 + (c >> 1)) * 2 + (c & 1)]
            = make_float2(-kn, -kn);
        __syncthreads();
        if (tid < KSZ_) {
            float q2 = 0.0f;
            #pragma unroll
            for (int c2 = 0; c2 < 8; c2++) {
                const float t = kns[tid * 8 + c2];
                q2 = fmaf(t, t, q2);
            }
            const float hh = 0.5f * q2;
            // slot 8, float2 half h: (h, h)
            ((float2*)g_slab)[(((tid * 32 + sp) * 9) + 8) * 2 + h]
                = make_float2(hh, hh);
        }
    }
}

// ---------------------------------------------------------------------------
// Main, j=8, 128-THREAD BLOCKS (one k per block, k/ch/m block-uniform):
//   grid = (64, 16):  blockIdx.y = b, blockIdx.x = tb*32 + k (tb in 0..1)
//   block = 128 thr = 4 warps: warp w = sg (S-quarter, 16 s each)
//   lane l handles t = tb*256 + l*8 + j, j in [0,8).
// Slab staged in smem (4.5KB, 2s-packed); 9 broadcast LDS.128 per 2 s.
// acc = hq2 + sum_c a[j+c]*(-q_c) pair;  out = p2 + 2*min.
// ---------------------------------------------------------------------------
__global__ __launch_bounds__(128, 8) void lsd_main(float* __restrict__ out) {
    const int tid = threadIdx.x;
    const int l   = tid & 31;
    const int sg  = tid >> 5;                 // 0..3 (warp-uniform)
    const int b   = blockIdx.y;
    const int tb  = blockIdx.x >> 5;          // 0..1
    const int k   = blockIdx.x & 31;          // BLOCK-uniform
    const int ch  = k >> 2;
    const int m   = k & 3;

    __shared__ float4 smq4[32 * 9];           // 4.5KB: [sp][9 float4]
    __shared__ float s_mn[3 * 256];           // 3KB: [sg-1][l*8 + j]

    // ---- slab copy: 288 float4 over 128 threads ----
    {
        const float4* __restrict__ gsl = g_slab + k * 288;
        smq4[tid]       = gsl[tid];
        smq4[tid + 128] = gsl[tid + 128];
        if (tid < 32) smq4[tid + 256] = gsl[tid + 256];
    }

    // ---- window loads: 16 floats via 4 aligned float4 LDGs (15 used) ----
    const int t0     = tb * 256 + l * 8;
    const int wstart = t0 + 8 * m;            // multiple of 8 -> 16B aligned
    const float4* __restrict__ xv =
        (const float4*)(g_xt + (b * C_ + ch) * T_ + wstart);
    const float4 A = xv[0], Bv = xv[1], Cv = xv[2], Dv = xv[3];
    float wv[15];
    wv[0]  = A.x;  wv[1]  = A.y;  wv[2]  = A.z;  wv[3]  = A.w;
    wv[4]  = Bv.x; wv[5]  = Bv.y; wv[6]  = Bv.z; wv[7]  = Bv.w;
    wv[8]  = Cv.x; wv[9]  = Cv.y; wv[10] = Cv.z; wv[11] = Cv.w;
    wv[12] = Dv.x; wv[13] = Dv.y; wv[14] = Dv.z;

    unsigned long long a[14];
    #pragma unroll
    for (int i = 0; i < 14; i++) a[i] = pk2(wv[i], wv[i + 1]);

    __syncthreads();

    // warp-uniform smem base for this warp's S-quarter (sp in [sg*8, sg*8+8))
    const ulonglong2* __restrict__ qv =
        (const ulonglong2*)smq4 + sg * 8 * 9;

    float mn[8];
    #pragma unroll
    for (int j = 0; j < 8; j++) mn[j] = 3.4e38f;

    #pragma unroll
    for (int p = 0; p < 8; p++) {
        const int base = p * 9;
        // s = 2p (slots 0..3) with hq.x; s = 2p+1 (slots 4..7) with hq.y
        const ulonglong2 hq = qv[base + 8];
        {
            const ulonglong2 u0 = qv[base + 0];
            const ulonglong2 u1 = qv[base + 1];
            const ulonglong2 u2 = qv[base + 2];
            const ulonglong2 u3 = qv[base + 3];
            step8(u0, u1, u2, u3, hq.x, a, mn);
        }
        {
            const ulonglong2 u0 = qv[base + 4];
            const ulonglong2 u1 = qv[base + 5];
            const ulonglong2 u2 = qv[base + 6];
            const ulonglong2 u3 = qv[base + 7];
            step8(u0, u1, u2, u3, hq.y, a, mn);
        }
    }

    // merge the four S-quarters (index within block: l*8 + j)
    if (sg >= 1) {
        #pragma unroll
        for (int j = 0; j < 8; j++)
            s_mn[(sg - 1) * 256 + l * 8 + j] = mn[j];
    }
    __syncthreads();
    if (sg == 0) {
        // sliding-window p2: p2_{j+1} = p2_j - w_j^2 + w_{j+8}^2
        float p2j[8];
        float p2 = 0.0f;
        #pragma unroll
        for (int c = 0; c < 8; c++) p2 = fmaf(wv[c], wv[c], p2);
        p2j[0] = p2;
        #pragma unroll
        for (int j = 1; j < 8; j++) {
            p2 = fmaf(wv[j + 7], wv[j + 7], fmaf(-wv[j - 1], wv[j - 1], p2));
            p2j[j] = p2;
        }

        #pragma unroll
        for (int j = 0; j < 8; j++) {
            const int t = t0 + j;
            if (t < TOUT) {
                const int base = l * 8 + j;
                float v = mn[j];
                v = fminf(v, s_mn[0 * 256 + base]);
                v = fminf(v, s_mn[1 * 256 + base]);
                v = fminf(v, s_mn[2 * 256 + base]);
                out[(b * TOUT + t) * KSZ_ + k] = fmaf(2.0f, v, p2j[j]);
            }
        }
    }
}

extern "C" void kernel_launch(void* const* d_in, const int* in_sizes, int n_in,
                              void* d_out, int out_size) {
    const float* x    = (const float*)d_in[0];   // (16, 512, 8) f32
    const float* kern = (const float*)d_in[1];   // (64, 32, 8) f32
    float* out = (float*)d_out;                  // (16, 481, 32) f32

    lsd_prep<<<B_ * C_ + S_, 256>>>(x, kern);
    dim3 grid(64, B_);                           // (tb*32 + k) x b
    lsd_main<<<grid, 128>>>(out);
}